// round 4
// baseline (speedup 1.0000x reference)
#include <cuda_runtime.h>
#include <cuda_bf16.h>
#include <math.h>

// Problem constants
#define NTOK 4096     // B*T
#define DD   512      // D
#define HH   1024     // H
#define EE   8        // experts
#define NKP  8192     // NTOK * K slots
#define OUTD 512
#define BM 128
#define BN 128

// ---- scratch (static device globals; no runtime allocation) ----
__device__ float g_weff[EE * DD * DD];               // folded router weights [E][D][D]
__device__ float g_beff[EE * DD];                    // folded router bias
__device__ float g_re[(size_t)EE * NTOK * DD];       // router embeddings [E][N][D]
__device__ float g_T1[(size_t)NKP * HH];             // expert activations ping
__device__ float g_T2[(size_t)NKP * HH];             // expert activations pong
__device__ float g_comb[(size_t)NTOK * HH];          // gated combination
__device__ float g_probs[NTOK * 2];                  // slot probs
__device__ int   g_sel[NKP];                         // slot -> expert
__device__ int   g_cnt[EE];                          // tokens per expert
__device__ int   g_pairs[EE * NKP];                  // per-expert slot lists

__device__ __forceinline__ float gelu_f(float v) {
    return 0.5f * v * (1.0f + erff(v * 0.7071067811865475f));
}

__global__ void moe_init_kernel() {
    if (threadIdx.x < EE) g_cnt[threadIdx.x] = 0;
}

// beff[e][j] = sum_d bmap[e*D+d] * Wr[d][j] + br[j]
__global__ void moe_beff_kernel(const float* __restrict__ bmap,
                                const float* __restrict__ Wr,
                                const float* __restrict__ br) {
    int e = blockIdx.x;
    int j = blockIdx.y * 256 + threadIdx.x;
    float s = br[j];
    for (int d = 0; d < DD; d++) s += bmap[e * DD + d] * Wr[d * DD + j];
    g_beff[e * DD + j] = s;
}

// Generic batched GEMM: C[z][m][n] = act(sum_k A[z][m][k]*B[z][k][n] + bias[z][n])
// All M, N multiples of 128, K multiple of 8. Tiling 128x128x8, 256 thr, 8x8/thread.
__global__ __launch_bounds__(256) void moe_gemm_bat(
    const float* __restrict__ A, long long sA, int lda,
    const float* __restrict__ B, long long sB, int ldb,
    float* __restrict__ C, long long sC, int ldc,
    const float* __restrict__ bias, long long sBias,
    int Kd, int act)
{
    int z = blockIdx.z;
    const float* Az = A + (size_t)z * sA;
    const float* Bz = B + (size_t)z * sB;
    float* Cz = C + (size_t)z * sC;
    const float* bz = bias ? bias + (size_t)z * sBias : nullptr;

    int m0 = blockIdx.x * BM, n0 = blockIdx.y * BN;
    int tid = threadIdx.x;

    __shared__ float As[8][BM];
    __shared__ float Bs[8][BN];

    int ar = tid >> 1, ak = (tid & 1) * 4;
    int brw = tid >> 5, bc = (tid & 31) * 4;
    int ty = tid >> 4, tx = tid & 15;

    float acc[8][8];
#pragma unroll
    for (int i = 0; i < 8; i++)
#pragma unroll
        for (int j = 0; j < 8; j++) acc[i][j] = 0.f;

    const float* Aptr = Az + (size_t)(m0 + ar) * lda + ak;
    const float* Bptr = Bz + (size_t)brw * ldb + n0 + bc;

    for (int k0 = 0; k0 < Kd; k0 += 8) {
        float4 av = *(const float4*)(Aptr + k0);
        float4 bv = *(const float4*)(Bptr + (size_t)k0 * ldb);
        As[ak + 0][ar] = av.x; As[ak + 1][ar] = av.y;
        As[ak + 2][ar] = av.z; As[ak + 3][ar] = av.w;
        *(float4*)&Bs[brw][bc] = bv;
        __syncthreads();
#pragma unroll
        for (int kk = 0; kk < 8; kk++) {
            float a[8], b[8];
            *(float4*)(a)     = *(const float4*)&As[kk][ty * 8];
            *(float4*)(a + 4) = *(const float4*)&As[kk][ty * 8 + 4];
            *(float4*)(b)     = *(const float4*)&Bs[kk][tx * 8];
            *(float4*)(b + 4) = *(const float4*)&Bs[kk][tx * 8 + 4];
#pragma unroll
            for (int i = 0; i < 8; i++)
#pragma unroll
                for (int j = 0; j < 8; j++) acc[i][j] = fmaf(a[i], b[j], acc[i][j]);
        }
        __syncthreads();
    }

#pragma unroll
    for (int i = 0; i < 8; i++) {
        int m = m0 + ty * 8 + i;
        float* crow = Cz + (size_t)m * ldc + n0 + tx * 8;
#pragma unroll
        for (int j = 0; j < 8; j++) {
            float v = acc[i][j];
            if (bz) v += bz[n0 + tx * 8 + j];
            if (act) v = gelu_f(v);
            crow[j] = v;
        }
    }
}

// Gating: dist per expert, select top-2 of -exp(-dist) (ref semantics),
// probs, scatter slot into per-expert lists.
__global__ void moe_gate_kernel(const float* __restrict__ x) {
    int n = blockIdx.x;
    __shared__ float xs[DD];
    __shared__ float sdist[EE];
    int tid = threadIdx.x;
    xs[tid] = x[(size_t)n * DD + tid];
    xs[tid + 256] = x[(size_t)n * DD + tid + 256];
    __syncthreads();
    int w = tid >> 5, lane = tid & 31;
    const float* rr = g_re + ((size_t)w * NTOK + n) * DD;
    float p = 0.f;
    for (int j = lane; j < DD; j += 32) {
        float d = xs[j] - rr[j];
        p += d * d;
    }
#pragma unroll
    for (int o = 16; o; o >>= 1) p += __shfl_xor_sync(0xffffffffu, p, o);
    if (lane == 0) sdist[w] = p;
    __syncthreads();
    if (tid == 0) {
        float msim[EE];
#pragma unroll
        for (int e = 0; e < EE; e++) msim[e] = -expf(-sqrtf(sdist[e]));
        int i0 = 0;
#pragma unroll
        for (int e = 1; e < EE; e++) if (msim[e] > msim[i0]) i0 = e;
        int i1 = (i0 == 0) ? 1 : 0;
#pragma unroll
        for (int e = 0; e < EE; e++)
            if (e != i0 && msim[e] > msim[i1]) i1 = e;
        float v0 = msim[i0], v1 = msim[i1];
        float inv = 1.f / (v0 + v1);
        float p0 = v0 * inv, p1 = v1 * inv;
        g_probs[2 * n + 0] = p0;
        g_probs[2 * n + 1] = p1;
        g_sel[2 * n + 0] = i0;
        g_sel[2 * n + 1] = i1;
        int pos = atomicAdd(&g_cnt[i0], 1);
        g_pairs[i0 * NKP + pos] = 2 * n + 0;
        pos = atomicAdd(&g_cnt[i1], 1);
        g_pairs[i1 * NKP + pos] = 2 * n + 1;
    }
}

// Gathered expert GEMM: rows = this expert's slot list, B = W[e], epilogue gelu.
// Output row = slot index (deterministic regardless of list order).
__global__ __launch_bounds__(256) void moe_expert_gemm(
    const float* __restrict__ Xtok, const float* __restrict__ Tin,
    const float* __restrict__ W, const float* __restrict__ bvec,
    float* __restrict__ Tout, int Kd, int stage1)
{
    int e = blockIdx.z;
    int cnt = g_cnt[e];
    int m0 = blockIdx.x * BM;
    if (m0 >= cnt) return;
    int n0 = blockIdx.y * BN;
    int tid = threadIdx.x;

    __shared__ float As[8][BM];
    __shared__ float Bs[8][BN];
    __shared__ int sslot[BM];

    if (tid < BM) {
        int m = m0 + tid;
        sslot[tid] = (m < cnt) ? g_pairs[e * NKP + m] : -1;
    }
    __syncthreads();

    int ar = tid >> 1, ak = (tid & 1) * 4;
    int brw = tid >> 5, bc = (tid & 31) * 4;
    int ty = tid >> 4, tx = tid & 15;

    const float* Aptr = nullptr;
    {
        int s = sslot[ar];
        if (s >= 0)
            Aptr = stage1 ? (Xtok + (size_t)(s >> 1) * DD + ak)
                          : (Tin + (size_t)s * HH + ak);
    }
    const float* Bptr = W + (size_t)e * Kd * HH + (size_t)brw * HH + n0 + bc;

    float acc[8][8];
#pragma unroll
    for (int i = 0; i < 8; i++)
#pragma unroll
        for (int j = 0; j < 8; j++) acc[i][j] = 0.f;

    for (int k0 = 0; k0 < Kd; k0 += 8) {
        float4 av = Aptr ? *(const float4*)(Aptr + k0) : make_float4(0.f, 0.f, 0.f, 0.f);
        float4 bv = *(const float4*)(Bptr + (size_t)k0 * HH);
        As[ak + 0][ar] = av.x; As[ak + 1][ar] = av.y;
        As[ak + 2][ar] = av.z; As[ak + 3][ar] = av.w;
        *(float4*)&Bs[brw][bc] = bv;
        __syncthreads();
#pragma unroll
        for (int kk = 0; kk < 8; kk++) {
            float a[8], b[8];
            *(float4*)(a)     = *(const float4*)&As[kk][ty * 8];
            *(float4*)(a + 4) = *(const float4*)&As[kk][ty * 8 + 4];
            *(float4*)(b)     = *(const float4*)&Bs[kk][tx * 8];
            *(float4*)(b + 4) = *(const float4*)&Bs[kk][tx * 8 + 4];
#pragma unroll
            for (int i = 0; i < 8; i++)
#pragma unroll
                for (int j = 0; j < 8; j++) acc[i][j] = fmaf(a[i], b[j], acc[i][j]);
        }
        __syncthreads();
    }

    const float* bp = bvec + (size_t)e * HH + n0 + tx * 8;
#pragma unroll
    for (int i = 0; i < 8; i++) {
        int m = m0 + ty * 8 + i;
        if (m >= cnt) break;
        int s = sslot[ty * 8 + i];
        float* crow = Tout + (size_t)s * HH + n0 + tx * 8;
#pragma unroll
        for (int j = 0; j < 8; j++)
            crow[j] = gelu_f(acc[i][j] + bp[j]);
    }
}

// LayerNorm over `width` per row. useSel: per-row expert gamma/beta offset.
__global__ void moe_ln_kernel(const float* __restrict__ X, float* __restrict__ Y,
                              const float* __restrict__ gamma, const float* __restrict__ beta,
                              int width, int useSel)
{
    int row = blockIdx.x;
    int tid = threadIdx.x;
    const float* xr = X + (size_t)row * width;
    int per = width >> 8;               // width/256 (2 or 4)
    float lv[4];
    float s = 0.f, sq = 0.f;
    for (int i = 0; i < per; i++) {
        float v = xr[tid + i * 256];
        lv[i] = v; s += v; sq += v * v;
    }
    __shared__ float r1[256], r2[256];
    r1[tid] = s; r2[tid] = sq;
    __syncthreads();
    for (int o = 128; o > 0; o >>= 1) {
        if (tid < o) { r1[tid] += r1[tid + o]; r2[tid] += r2[tid + o]; }
        __syncthreads();
    }
    float mu = r1[0] / width;
    float var = r2[0] / width - mu * mu;
    float rstd = rsqrtf(var + 1e-5f);
    int gofs = useSel ? g_sel[row] * width : 0;
    float* yr = Y + (size_t)row * width;
    for (int i = 0; i < per; i++) {
        int c = tid + i * 256;
        yr[c] = (lv[i] - mu) * rstd * gamma[gofs + c] + beta[gofs + c];
    }
}

// combined[n][h] = p0 * T[2n][h] + p1 * T[2n+1][h]
__global__ void moe_combine_kernel(const float* __restrict__ T) {
    int idx = blockIdx.x * 256 + threadIdx.x;
    int n = idx >> 10, h = idx & (HH - 1);
    float p0 = g_probs[2 * n], p1 = g_probs[2 * n + 1];
    g_comb[idx] = p0 * T[(size_t)(2 * n) * HH + h] + p1 * T[(size_t)(2 * n + 1) * HH + h];
}

// Deterministic single-block entropy reduction.
__global__ void moe_ent_kernel(float* __restrict__ outp) {
    int tid = threadIdx.x;
    double s0 = 0, s1 = 0, sp = 0;
    for (int n = tid; n < NTOK; n += 256) {
        float p0 = g_probs[2 * n], p1 = g_probs[2 * n + 1];
        s0 += p0; s1 += p1;
        sp += (double)(p0 * logf(p0 + 1e-6f) + p1 * logf(p1 + 1e-6f));
    }
    __shared__ double a0[256], a1[256], ap[256];
    a0[tid] = s0; a1[tid] = s1; ap[tid] = sp;
    __syncthreads();
    for (int o = 128; o > 0; o >>= 1) {
        if (tid < o) { a0[tid] += a0[tid + o]; a1[tid] += a1[tid + o]; ap[tid] += ap[tid + o]; }
        __syncthreads();
    }
    if (tid == 0) {
        float pm0 = (float)(a0[0] / NTOK);
        float pm1 = (float)(a1[0] / NTOK);
        float t1 = pm0 * logf(pm0 + 1e-6f) + pm1 * logf(pm1 + 1e-6f);
        outp[0] = t1 - (float)(ap[0] / NTOK);
    }
}

extern "C" void kernel_launch(void* const* d_in, const int* in_sizes, int n_in,
                              void* d_out, int out_size) {
    const float* x    = (const float*)d_in[0];
    const float* Wmap = (const float*)d_in[1];
    const float* bmap = (const float*)d_in[2];
    const float* Wr   = (const float*)d_in[3];
    const float* br   = (const float*)d_in[4];
    const float* W1   = (const float*)d_in[5];
    const float* b1   = (const float*)d_in[6];
    const float* g1   = (const float*)d_in[7];
    const float* be1  = (const float*)d_in[8];
    const float* W2   = (const float*)d_in[9];
    const float* b2   = (const float*)d_in[10];
    const float* g2   = (const float*)d_in[11];
    const float* be2  = (const float*)d_in[12];
    const float* W3   = (const float*)d_in[13];
    const float* b3   = (const float*)d_in[14];
    const float* g3   = (const float*)d_in[15];
    const float* be3  = (const float*)d_in[16];
    const float* Wo   = (const float*)d_in[17];
    const float* bo   = (const float*)d_in[18];
    const float* go   = (const float*)d_in[19];
    const float* beo  = (const float*)d_in[20];
    float* out = (float*)d_out;

    float *weffp, *beffp, *rep, *t1p, *t2p, *combp;
    cudaGetSymbolAddress((void**)&weffp, g_weff);
    cudaGetSymbolAddress((void**)&beffp, g_beff);
    cudaGetSymbolAddress((void**)&rep,   g_re);
    cudaGetSymbolAddress((void**)&t1p,   g_T1);
    cudaGetSymbolAddress((void**)&t2p,   g_T2);
    cudaGetSymbolAddress((void**)&combp, g_comb);

    moe_init_kernel<<<1, 32>>>();

    // Folded router weights: Weff[e] = Wmap[:, e*D:(e+1)*D] @ Wr
    {
        dim3 grid(DD / BM, DD / BN, EE);
        moe_gemm_bat<<<grid, 256>>>(Wmap, (long long)DD, DD * EE,
                                    Wr, 0LL, DD,
                                    weffp, (long long)DD * DD, DD,
                                    nullptr, 0LL, DD, 0);
    }
    moe_beff_kernel<<<dim3(EE, DD / 256), 256>>>(bmap, Wr, br);

    // re[e] = x @ Weff[e] + beff[e]
    {
        dim3 grid(NTOK / BM, DD / BN, EE);
        moe_gemm_bat<<<grid, 256>>>(x, 0LL, DD,
                                    weffp, (long long)DD * DD, DD,
                                    rep, (long long)NTOK * DD, DD,
                                    beffp, (long long)DD, DD, 0);
    }

    // Gating + scatter
    moe_gate_kernel<<<NTOK, 256>>>(x);

    // Expert MLP (sparse: only selected (token, expert) pairs)
    {
        dim3 grid(NKP / BM, HH / BN, EE);
        moe_expert_gemm<<<grid, 256>>>(x, nullptr, W1, b1, t1p, DD, 1);
        moe_ln_kernel<<<NKP, 256>>>(t1p, t1p, g1, be1, HH, 1);
        moe_expert_gemm<<<grid, 256>>>(nullptr, t1p, W2, b2, t2p, HH, 0);
        moe_ln_kernel<<<NKP, 256>>>(t2p, t2p, g2, be2, HH, 1);
        moe_expert_gemm<<<grid, 256>>>(nullptr, t2p, W3, b3, t1p, HH, 0);
        moe_ln_kernel<<<NKP, 256>>>(t1p, t1p, g3, be3, HH, 1);
    }

    // Gated combine
    moe_combine_kernel<<<(NTOK * HH) / 256, 256>>>(t1p);

    // out_linear: gelu(combined @ Wo + bo), then LN -> d_out
    {
        dim3 grid(NTOK / BM, OUTD / BN, 1);
        moe_gemm_bat<<<grid, 256>>>(combp, 0LL, HH,
                                    Wo, 0LL, OUTD,
                                    t2p, 0LL, OUTD,
                                    bo, 0LL, HH, 1);
    }
    moe_ln_kernel<<<NTOK, 256>>>(t2p, out, go, beo, OUTD, 0);

    // entropy scalar appended after the [N, OUT] output
    if (out_size > NTOK * OUTD)
        moe_ent_kernel<<<1, 256>>>(out + (size_t)NTOK * OUTD);
}

// round 10
// speedup vs baseline: 1.9362x; 1.9362x over previous
#include <cuda_runtime.h>
#include <cuda_bf16.h>
#include <math.h>
#include <stdint.h>

// Problem constants
#define NTOK 4096     // B*T
#define DD   512
#define HH   1024
#define EE   8
#define NKP  8192     // NTOK*K slots
#define OUTD 512

// ---------------- fp32 scratch ----------------
__device__ float g_weff[EE * DD * DD];
__device__ float g_beff[EE * DD];
__device__ float g_re[(size_t)EE * NTOK * DD];
__device__ float g_T1[(size_t)NKP * HH];
__device__ float g_T2[(size_t)NKP * HH];
__device__ float g_comb[(size_t)NTOK * HH];
__device__ float g_probs[NTOK * 2];
__device__ int   g_sel[NKP];
__device__ int   g_cnt[EE];
__device__ int   g_pairs[EE * NKP];

// ---------------- bf16 split weights (K-major: [N][K]) ----------------
__device__ __nv_bfloat16 g_wrt_h[DD * DD],              g_wrt_l[DD * DD];
__device__ __nv_bfloat16 g_wefft_h[EE * DD * DD],       g_wefft_l[EE * DD * DD];
__device__ __nv_bfloat16 g_w1t_h[EE * HH * DD],         g_w1t_l[EE * HH * DD];
__device__ __nv_bfloat16 g_w2t_h[(size_t)EE * HH * HH], g_w2t_l[(size_t)EE * HH * HH];
__device__ __nv_bfloat16 g_w3t_h[(size_t)EE * HH * HH], g_w3t_l[(size_t)EE * HH * HH];
__device__ __nv_bfloat16 g_wot_h[OUTD * HH],            g_wot_l[OUTD * HH];

__device__ __forceinline__ float gelu_f(float v) {
    return 0.5f * v * (1.0f + erff(v * 0.7071067811865475f));
}

__device__ __forceinline__ uint32_t pack_bf2(__nv_bfloat16 a, __nv_bfloat16 b) {
    return (uint32_t)__bfloat16_as_ushort(a) | ((uint32_t)__bfloat16_as_ushort(b) << 16);
}

__device__ __forceinline__ void split2(float x, float y, uint32_t& hi, uint32_t& lo) {
    __nv_bfloat16 hx = __float2bfloat16(x), hy = __float2bfloat16(y);
    __nv_bfloat16 lx = __float2bfloat16(x - __bfloat162float(hx));
    __nv_bfloat16 ly = __float2bfloat16(y - __bfloat162float(hy));
    hi = pack_bf2(hx, hy);
    lo = pack_bf2(lx, ly);
}

__device__ __forceinline__ void mma_bf16(float* d, const uint32_t* a, uint32_t b0, uint32_t b1) {
    asm volatile(
        "mma.sync.aligned.m16n8k16.row.col.f32.bf16.bf16.f32 "
        "{%0,%1,%2,%3}, {%4,%5,%6,%7}, {%8,%9}, {%0,%1,%2,%3};"
        : "+f"(d[0]), "+f"(d[1]), "+f"(d[2]), "+f"(d[3])
        : "r"(a[0]), "r"(a[1]), "r"(a[2]), "r"(a[3]), "r"(b0), "r"(b1));
}

// ================= kernels =================

__global__ void moe_init_kernel() {
    if (threadIdx.x < EE) g_cnt[threadIdx.x] = 0;
}

// beff[e][j] = sum_d bmap[e*D+d] * Wr[d][j] + br[j]
__global__ void moe_beff_kernel(const float* __restrict__ bmap,
                                const float* __restrict__ Wr,
                                const float* __restrict__ br) {
    int e = blockIdx.x;
    int j = blockIdx.y * 256 + threadIdx.x;
    float s = br[j];
    for (int d = 0; d < DD; d++) s += bmap[e * DD + d] * Wr[d * DD + j];
    g_beff[e * DD + j] = s;
}

// Transpose + bf16 split: src [rows=K, cols=N] fp32 -> out [N][K] hi/lo bf16
__global__ void moe_split_w(const float* __restrict__ src, int lda, long long sBatch,
                            int rows, int cols,
                            __nv_bfloat16* __restrict__ hi, __nv_bfloat16* __restrict__ lo) {
    __shared__ float tile[32][33];
    int z = blockIdx.z;
    const float* S = src + (size_t)z * sBatch;
    size_t obase = (size_t)z * rows * cols;
    int n0 = blockIdx.x * 32, k0 = blockIdx.y * 32;
    for (int i = threadIdx.y; i < 32; i += 8)
        tile[i][threadIdx.x] = S[(size_t)(k0 + i) * lda + n0 + threadIdx.x];
    __syncthreads();
    for (int i = threadIdx.y; i < 32; i += 8) {
        float v = tile[threadIdx.x][i];                 // = S[k0+tx][n0+i]
        __nv_bfloat16 h = __float2bfloat16(v);
        __nv_bfloat16 l = __float2bfloat16(v - __bfloat162float(h));
        size_t o = obase + (size_t)(n0 + i) * rows + k0 + threadIdx.x;
        hi[o] = h; lo[o] = l;
    }
}

// ---- split-bf16 mma.sync GEMM ----
// C[slot(m)][n] = act( sum_k A_row(m)[k] * B[z][n][k] + bias[z][n] )
// gmode: 0 dense (A + z*sA + m*lda, slot=m), 1 gather x rows (slot>>1), 2 gather slot rows.
// 128x128 tile, 256 thr, 8 warps (4m x 2n), warp tile 32x64, K-chunks of 32.
#define ASTR 40   // padded smem row stride (bf16 elems) -> conflict-free frags
__global__ __launch_bounds__(256, 2) void moe_mma_gemm(
    const float* __restrict__ A, long long sA, int lda, int gmode,
    const __nv_bfloat16* __restrict__ Bh, const __nv_bfloat16* __restrict__ Bl, long long sB,
    float* __restrict__ C, long long sC, int ldc,
    const float* __restrict__ bias, long long sBias,
    int Kd, int act, int useCnt)
{
    int e = blockIdx.z;
    int cnt = useCnt ? g_cnt[e] : 0x40000000;
    int m0 = blockIdx.x * 128;
    if (m0 >= cnt) return;
    int n0 = blockIdx.y * 128;
    int tid = threadIdx.x;
    int wid = tid >> 5, lane = tid & 31;

    __shared__ __nv_bfloat16 sAh[128 * ASTR];
    __shared__ __nv_bfloat16 sAl[128 * ASTR];
    __shared__ __nv_bfloat16 sBh[128 * ASTR];
    __shared__ __nv_bfloat16 sBl[128 * ASTR];
    __shared__ const float* rp[128];
    __shared__ int sl[128];

    if (tid < 128) {
        int m = m0 + tid;
        int slot = -1;
        const float* p = nullptr;
        if (gmode == 0) { slot = m; p = A + (size_t)e * sA + (size_t)m * lda; }
        else if (m < cnt) {
            slot = g_pairs[e * NKP + m];
            p = (gmode == 1) ? A + (size_t)(slot >> 1) * lda
                             : A + (size_t)slot * lda;
        }
        rp[tid] = p; sl[tid] = slot;
    }
    __syncthreads();

    const __nv_bfloat16* Bzh = Bh + (size_t)e * sB;
    const __nv_bfloat16* Bzl = Bl + (size_t)e * sB;

    int wm = wid >> 1;           // 0..3 (m)
    int wn = wid & 1;            // 0..1 (n)
    int row2 = tid >> 1;         // 0..127 load row
    int cb = (tid & 1) * 16;     // 0 or 16 load col base

    float acc[2][8][4];
#pragma unroll
    for (int i = 0; i < 2; i++)
#pragma unroll
        for (int j = 0; j < 8; j++)
#pragma unroll
            for (int q = 0; q < 4; q++) acc[i][j][q] = 0.f;

    const float* ap = rp[row2];
    const __nv_bfloat16* bph = Bzh + (size_t)(n0 + row2) * Kd + cb;
    const __nv_bfloat16* bpl = Bzl + (size_t)(n0 + row2) * Kd + cb;

    int nch = Kd >> 5;
    for (int c = 0; c < nch; c++) {
        int k0 = c << 5;
        // ---- A: fp32 load -> split bf16 hi/lo into smem ----
        {
            float4 v[4];
            if (ap) {
                const float* q = ap + k0 + cb;
                v[0] = *(const float4*)(q);
                v[1] = *(const float4*)(q + 4);
                v[2] = *(const float4*)(q + 8);
                v[3] = *(const float4*)(q + 12);
            } else {
                v[0] = v[1] = v[2] = v[3] = make_float4(0.f, 0.f, 0.f, 0.f);
            }
            int base = row2 * ASTR + cb;
#pragma unroll
            for (int q = 0; q < 4; q++) {
                uint32_t h0, l0, h1, l1;
                split2(v[q].x, v[q].y, h0, l0);
                split2(v[q].z, v[q].w, h1, l1);
                *(uint2*)&sAh[base + q * 4] = make_uint2(h0, h1);
                *(uint2*)&sAl[base + q * 4] = make_uint2(l0, l1);
            }
        }
        // ---- B: bf16 hi/lo straight copies ----
        {
            int base = row2 * ASTR + cb;
            *(uint4*)&sBh[base]     = *(const uint4*)(bph + k0);
            *(uint4*)&sBh[base + 8] = *(const uint4*)(bph + k0 + 8);
            *(uint4*)&sBl[base]     = *(const uint4*)(bpl + k0);
            *(uint4*)&sBl[base + 8] = *(const uint4*)(bpl + k0 + 8);
        }
        __syncthreads();

        // ---- compute: 3 split passes x 2 k16 steps x (2m x 8n) mma ----
#pragma unroll
        for (int pass = 0; pass < 3; pass++) {
            const __nv_bfloat16* As = (pass == 2) ? sAl : sAh;
            const __nv_bfloat16* Bs = (pass == 1) ? sBl : sBh;
#pragma unroll
            for (int ks = 0; ks < 2; ks++) {
                int kb = ks * 16 + (lane & 3) * 2;
                uint32_t afr[2][4];
#pragma unroll
                for (int mi = 0; mi < 2; mi++) {
                    int mr = wm * 32 + mi * 16 + (lane >> 2);
                    const __nv_bfloat16* s = As + mr * ASTR + kb;
                    afr[mi][0] = *(const uint32_t*)(s);
                    afr[mi][1] = *(const uint32_t*)(s + 8 * ASTR);
                    afr[mi][2] = *(const uint32_t*)(s + 8);
                    afr[mi][3] = *(const uint32_t*)(s + 8 * ASTR + 8);
                }
#pragma unroll
                for (int ni = 0; ni < 8; ni++) {
                    int nr = wn * 64 + ni * 8 + (lane >> 2);
                    const __nv_bfloat16* s = Bs + nr * ASTR + kb;
                    uint32_t b0 = *(const uint32_t*)(s);
                    uint32_t b1 = *(const uint32_t*)(s + 8);
                    mma_bf16(acc[0][ni], afr[0], b0, b1);
                    mma_bf16(acc[1][ni], afr[1], b0, b1);
                }
            }
        }
        __syncthreads();
    }

    // ---- epilogue: bias (+GELU) -> gmem at gathered slots ----
    float* Cz = C + (size_t)e * sC;
    const float* bz = bias ? bias + (size_t)e * sBias : nullptr;
#pragma unroll
    for (int mi = 0; mi < 2; mi++) {
        int ml0 = wm * 32 + mi * 16 + (lane >> 2);
        int s0 = sl[ml0];
        int s1 = sl[ml0 + 8];
#pragma unroll
        for (int ni = 0; ni < 8; ni++) {
            int n = n0 + wn * 64 + ni * 8 + (lane & 3) * 2;
            float bv0 = bz ? bz[n] : 0.f;
            float bv1 = bz ? bz[n + 1] : 0.f;
            if (s0 >= 0) {
                float v0 = acc[mi][ni][0] + bv0;
                float v1 = acc[mi][ni][1] + bv1;
                if (act) { v0 = gelu_f(v0); v1 = gelu_f(v1); }
                *(float2*)(Cz + (size_t)s0 * ldc + n) = make_float2(v0, v1);
            }
            if (s1 >= 0) {
                float v0 = acc[mi][ni][2] + bv0;
                float v1 = acc[mi][ni][3] + bv1;
                if (act) { v0 = gelu_f(v0); v1 = gelu_f(v1); }
                *(float2*)(Cz + (size_t)s1 * ldc + n) = make_float2(v0, v1);
            }
        }
    }
}

// Gating: dist per expert, top-2 of -exp(-dist) (ref semantics), scatter slots.
__global__ void moe_gate_kernel(const float* __restrict__ x) {
    int n = blockIdx.x;
    __shared__ float xs[DD];
    __shared__ float sdist[EE];
    int tid = threadIdx.x;
    xs[tid] = x[(size_t)n * DD + tid];
    xs[tid + 256] = x[(size_t)n * DD + tid + 256];
    __syncthreads();
    int w = tid >> 5, lane = tid & 31;
    const float* rr = g_re + ((size_t)w * NTOK + n) * DD;
    float p = 0.f;
    for (int j = lane; j < DD; j += 32) {
        float d = xs[j] - rr[j];
        p += d * d;
    }
#pragma unroll
    for (int o = 16; o; o >>= 1) p += __shfl_xor_sync(0xffffffffu, p, o);
    if (lane == 0) sdist[w] = p;
    __syncthreads();
    if (tid == 0) {
        float msim[EE];
#pragma unroll
        for (int e = 0; e < EE; e++) msim[e] = -expf(-sqrtf(sdist[e]));
        int i0 = 0;
#pragma unroll
        for (int e = 1; e < EE; e++) if (msim[e] > msim[i0]) i0 = e;
        int i1 = (i0 == 0) ? 1 : 0;
#pragma unroll
        for (int e = 0; e < EE; e++)
            if (e != i0 && msim[e] > msim[i1]) i1 = e;
        float v0 = msim[i0], v1 = msim[i1];
        float inv = 1.f / (v0 + v1);
        g_probs[2 * n + 0] = v0 * inv;
        g_probs[2 * n + 1] = v1 * inv;
        g_sel[2 * n + 0] = i0;
        g_sel[2 * n + 1] = i1;
        int pos = atomicAdd(&g_cnt[i0], 1);
        g_pairs[i0 * NKP + pos] = 2 * n + 0;
        pos = atomicAdd(&g_cnt[i1], 1);
        g_pairs[i1 * NKP + pos] = 2 * n + 1;
    }
}

// LayerNorm; useSel: per-row expert gamma/beta.
__global__ void moe_ln_kernel(const float* __restrict__ X, float* __restrict__ Y,
                              const float* __restrict__ gamma, const float* __restrict__ beta,
                              int width, int useSel)
{
    int row = blockIdx.x;
    int tid = threadIdx.x;
    const float* xr = X + (size_t)row * width;
    int per = width >> 8;
    float lv[4];
    float s = 0.f, sq = 0.f;
    for (int i = 0; i < per; i++) {
        float v = xr[tid + i * 256];
        lv[i] = v; s += v; sq += v * v;
    }
    __shared__ float r1[256], r2[256];
    r1[tid] = s; r2[tid] = sq;
    __syncthreads();
    for (int o = 128; o > 0; o >>= 1) {
        if (tid < o) { r1[tid] += r1[tid + o]; r2[tid] += r2[tid + o]; }
        __syncthreads();
    }
    float mu = r1[0] / width;
    float var = r2[0] / width - mu * mu;
    float rstd = rsqrtf(var + 1e-5f);
    int gofs = useSel ? g_sel[row] * width : 0;
    float* yr = Y + (size_t)row * width;
    for (int i = 0; i < per; i++) {
        int c = tid + i * 256;
        yr[c] = (lv[i] - mu) * rstd * gamma[gofs + c] + beta[gofs + c];
    }
}

__global__ void moe_combine_kernel(const float* __restrict__ T) {
    int idx = blockIdx.x * 256 + threadIdx.x;
    int n = idx >> 10, h = idx & (HH - 1);
    float p0 = g_probs[2 * n], p1 = g_probs[2 * n + 1];
    g_comb[idx] = p0 * T[(size_t)(2 * n) * HH + h] + p1 * T[(size_t)(2 * n + 1) * HH + h];
}

__global__ void moe_ent_kernel(float* __restrict__ outp) {
    int tid = threadIdx.x;
    double s0 = 0, s1 = 0, sp = 0;
    for (int n = tid; n < NTOK; n += 256) {
        float p0 = g_probs[2 * n], p1 = g_probs[2 * n + 1];
        s0 += p0; s1 += p1;
        sp += (double)(p0 * logf(p0 + 1e-6f) + p1 * logf(p1 + 1e-6f));
    }
    __shared__ double a0[256], a1[256], ap[256];
    a0[tid] = s0; a1[tid] = s1; ap[tid] = sp;
    __syncthreads();
    for (int o = 128; o > 0; o >>= 1) {
        if (tid < o) { a0[tid] += a0[tid + o]; a1[tid] += a1[tid + o]; ap[tid] += ap[tid + o]; }
        __syncthreads();
    }
    if (tid == 0) {
        float pm0 = (float)(a0[0] / NTOK);
        float pm1 = (float)(a1[0] / NTOK);
        float t1 = pm0 * logf(pm0 + 1e-6f) + pm1 * logf(pm1 + 1e-6f);
        outp[0] = t1 - (float)(ap[0] / NTOK);
    }
}

extern "C" void kernel_launch(void* const* d_in, const int* in_sizes, int n_in,
                              void* d_out, int out_size) {
    const float* x    = (const float*)d_in[0];
    const float* Wmap = (const float*)d_in[1];
    const float* bmap = (const float*)d_in[2];
    const float* Wr   = (const float*)d_in[3];
    const float* br   = (const float*)d_in[4];
    const float* W1   = (const float*)d_in[5];
    const float* b1   = (const float*)d_in[6];
    const float* g1   = (const float*)d_in[7];
    const float* be1  = (const float*)d_in[8];
    const float* W2   = (const float*)d_in[9];
    const float* b2   = (const float*)d_in[10];
    const float* g2   = (const float*)d_in[11];
    const float* be2  = (const float*)d_in[12];
    const float* W3   = (const float*)d_in[13];
    const float* b3   = (const float*)d_in[14];
    const float* g3   = (const float*)d_in[15];
    const float* be3  = (const float*)d_in[16];
    const float* Wo   = (const float*)d_in[17];
    const float* bo   = (const float*)d_in[18];
    const float* go   = (const float*)d_in[19];
    const float* beo  = (const float*)d_in[20];
    float* out = (float*)d_out;

    float *weffp, *beffp, *rep, *t1p, *t2p, *combp;
    cudaGetSymbolAddress((void**)&weffp, g_weff);
    cudaGetSymbolAddress((void**)&beffp, g_beff);
    cudaGetSymbolAddress((void**)&rep,   g_re);
    cudaGetSymbolAddress((void**)&t1p,   g_T1);
    cudaGetSymbolAddress((void**)&t2p,   g_T2);
    cudaGetSymbolAddress((void**)&combp, g_comb);

    __nv_bfloat16 *wrth, *wrtl, *wefth, *weftl, *w1th, *w1tl, *w2th, *w2tl, *w3th, *w3tl, *woth, *wotl;
    cudaGetSymbolAddress((void**)&wrth, g_wrt_h);    cudaGetSymbolAddress((void**)&wrtl, g_wrt_l);
    cudaGetSymbolAddress((void**)&wefth, g_wefft_h); cudaGetSymbolAddress((void**)&weftl, g_wefft_l);
    cudaGetSymbolAddress((void**)&w1th, g_w1t_h);    cudaGetSymbolAddress((void**)&w1tl, g_w1t_l);
    cudaGetSymbolAddress((void**)&w2th, g_w2t_h);    cudaGetSymbolAddress((void**)&w2tl, g_w2t_l);
    cudaGetSymbolAddress((void**)&w3th, g_w3t_h);    cudaGetSymbolAddress((void**)&w3tl, g_w3t_l);
    cudaGetSymbolAddress((void**)&woth, g_wot_h);    cudaGetSymbolAddress((void**)&wotl, g_wot_l);

    moe_init_kernel<<<1, 32>>>();

    dim3 tb(32, 8);
    // Split weights: transpose to [N][K] bf16 hi/lo
    moe_split_w<<<dim3(16, 16, 1), tb>>>(Wr, DD, 0, DD, DD, wrth, wrtl);
    moe_split_w<<<dim3(32, 16, EE), tb>>>(W1, HH, (long long)DD * HH, DD, HH, w1th, w1tl);
    moe_split_w<<<dim3(32, 32, EE), tb>>>(W2, HH, (long long)HH * HH, HH, HH, w2th, w2tl);
    moe_split_w<<<dim3(32, 32, EE), tb>>>(W3, HH, (long long)HH * HH, HH, HH, w3th, w3tl);
    moe_split_w<<<dim3(16, 32, 1), tb>>>(Wo, OUTD, 0, HH, OUTD, woth, wotl);

    // Weff[e] = Wmap[:, e*D:(e+1)*D] @ Wr  (A slice via e*sA column offset, lda=D*E)
    moe_mma_gemm<<<dim3(DD / 128, DD / 128, EE), 256>>>(
        Wmap, (long long)DD, DD * EE, 0,
        wrth, wrtl, 0LL,
        weffp, (long long)DD * DD, DD,
        nullptr, 0LL, DD, 0, 0);
    moe_beff_kernel<<<dim3(EE, DD / 256), 256>>>(bmap, Wr, br);
    moe_split_w<<<dim3(16, 16, EE), tb>>>(weffp, DD, (long long)DD * DD, DD, DD, wefth, weftl);

    // re[e] = x @ Weff[e] + beff[e]
    moe_mma_gemm<<<dim3(NTOK / 128, DD / 128, EE), 256>>>(
        x, 0LL, DD, 0,
        wefth, weftl, (long long)DD * DD,
        rep, (long long)NTOK * DD, DD,
        beffp, (long long)DD, DD, 0, 0);

    moe_gate_kernel<<<NTOK, 256>>>(x);

    // Expert MLP (sparse, gathered rows, HMMA tensor path)
    moe_mma_gemm<<<dim3(NKP / 128, HH / 128, EE), 256>>>(
        x, 0LL, DD, 1,
        w1th, w1tl, (long long)HH * DD,
        t1p, 0LL, HH,
        b1, (long long)HH, DD, 1, 1);
    moe_ln_kernel<<<NKP, 256>>>(t1p, t1p, g1, be1, HH, 1);
    moe_mma_gemm<<<dim3(NKP / 128, HH / 128, EE), 256>>>(
        t1p, 0LL, HH, 2,
        w2th, w2tl, (long long)HH * HH,
        t2p, 0LL, HH,
        b2, (long long)HH, HH, 1, 1);
    moe_ln_kernel<<<NKP, 256>>>(t2p, t2p, g2, be2, HH, 1);
    moe_mma_gemm<<<dim3(NKP / 128, HH / 128, EE), 256>>>(
        t2p, 0LL, HH, 2,
        w3th, w3tl, (long long)HH * HH,
        t1p, 0LL, HH,
        b3, (long long)HH, HH, 1, 1);
    moe_ln_kernel<<<NKP, 256>>>(t1p, t1p, g3, be3, HH, 1);

    moe_combine_kernel<<<(NTOK * HH) / 256, 256>>>(t1p);

    // out_linear: gelu(combined @ Wo + bo) then LN -> d_out
    moe_mma_gemm<<<dim3(NTOK / 128, OUTD / 128, 1), 256>>>(
        combp, 0LL, HH, 0,
        woth, wotl, 0LL,
        t2p, 0LL, OUTD,
        bo, 0LL, HH, 1, 0);
    moe_ln_kernel<<<NTOK, 256>>>(t2p, out, go, beo, OUTD, 0);

    if (out_size > NTOK * OUTD)
        moe_ent_kernel<<<1, 256>>>(out + (size_t)NTOK * OUTD);
}